// round 17
// baseline (speedup 1.0000x reference)
#include <cuda_runtime.h>
#include <math.h>
#include <stdint.h>

// Problem constants
#define TT   2048
#define BB   32
#define ICC  512
#define HCC  512
#define LLL  2

// Fused recurrence: 8 clusters x 16 CTAs. Cluster = 4 batches; CTA = 32 ch.
#define CS    16
#define NCTA  128
#define RTH   256
#define BPG   4
#define CPG   32

// Dynamic smem (bytes)
#define OFF_WI1  0               // [32][129] float4 (pad-129)
#define OFF_HS0  66048           // float[2][4*512] staged h0 (double buffer)
#define OFF_HS1  82432           // float[2][4*512] staged h1 (double buffer)
#define OFF_RED  98816           // float[3][1024]
#define FSMEM    111616

// Projection GEMM config
#define PBM 128
#define PBN 128
#define PBK 16
#define PLD (PBM + 4)

// ---------------------------------------------------------------------------
// Scratch (static device globals: allocation-free per harness rules)
// ---------------------------------------------------------------------------
__device__ float g_xproj[(size_t)TT * BB * HCC];
__device__ float g_h0[2][BB * HCC];   // L2 ping-pong: g_h0[s&1] = h0[s]
__device__ float g_h1[2][BB * HCC];   // L2 ping-pong: g_h1[s&1] = h1[s-1]

// ---------------------------------------------------------------------------
// Packed f32x2 helpers
// ---------------------------------------------------------------------------
__device__ __forceinline__ void fma2(unsigned long long& acc,
                                     unsigned long long a, unsigned long long b) {
    asm("fma.rn.f32x2 %0, %1, %2, %0;" : "+l"(acc) : "l"(a), "l"(b));
}
__device__ __forceinline__ unsigned long long dup2(float x) {
    unsigned long long d;
    asm("mov.b64 %0, {%1, %1};" : "=l"(d) : "f"(x));
    return d;
}
__device__ __forceinline__ float2 unpk(unsigned long long v) {
    float2 r;
    asm("mov.b64 {%0, %1}, %2;" : "=f"(r.x), "=f"(r.y) : "l"(v));
    return r;
}

// ---------------------------------------------------------------------------
// Cluster / mbarrier helpers (field-verified R9-R15)
// ---------------------------------------------------------------------------
__device__ __forceinline__ uint32_t smem_u32(const void* p) {
    uint32_t a;
    asm("{ .reg .u64 t; cvta.to.shared.u64 t, %1; cvt.u32.u64 %0, t; }"
        : "=r"(a) : "l"(p));
    return a;
}
__device__ __forceinline__ uint32_t mapa_u32(uint32_t a, uint32_t rank) {
    uint32_t r;
    asm("mapa.shared::cluster.u32 %0, %1, %2;" : "=r"(r) : "r"(a), "r"(rank));
    return r;
}
__device__ __forceinline__ void mbar_init(uint32_t a, uint32_t cnt) {
    asm volatile("mbarrier.init.shared.b64 [%0], %1;" :: "r"(a), "r"(cnt) : "memory");
}
__device__ __forceinline__ void mbar_arrive_remote(uint32_t a) {
    asm volatile("mbarrier.arrive.release.cluster.shared::cluster.b64 _, [%0];"
                 :: "r"(a) : "memory");
}
__device__ __forceinline__ void mbar_wait_parity(uint32_t a, uint32_t parity) {
    uint32_t done;
    asm volatile(
        "{\n\t.reg .pred p;\n\t"
        "mbarrier.try_wait.parity.acquire.cluster.shared::cta.b64 p, [%1], %2;\n\t"
        "selp.b32 %0, 1, 0, p;\n\t}"
        : "=r"(done) : "r"(a), "r"(parity) : "memory");
    if (!done) {
        asm volatile(
            "{\n\t.reg .pred P1;\n\t"
            "W_%=:\n\t"
            "mbarrier.try_wait.parity.acquire.cluster.shared::cta.b64 P1, [%0], %1, 0x989680;\n\t"
            "@P1 bra.uni D_%=;\n\t"
            "bra.uni W_%=;\n\t"
            "D_%=:\n\t}"
            :: "r"(a), "r"(parity) : "memory");
    }
}
#define CL_SYNC() do { \
    asm volatile("barrier.cluster.arrive.aligned;" ::: "memory"); \
    asm volatile("barrier.cluster.wait.aligned;"   ::: "memory"); } while (0)

// ---------------------------------------------------------------------------
// Projection GEMM (R12-proven, FFMA2). Layer 0 only.
// ---------------------------------------------------------------------------
__global__ __launch_bounds__(256, 2)
void proj_kernel(const float* __restrict__ Xin, const float* __restrict__ Wp,
                 const float* __restrict__ bp)
{
    __shared__ float As[PBK][PLD];
    __shared__ float Bs[PBK][PLD];

    const int t  = threadIdx.x;
    const int m0 = blockIdx.y * PBM;
    const int n0 = blockIdx.x * PBN;
    const int lr = t >> 1;
    const int lc = (t & 1) << 3;
    const int tx = t & 15;
    const int ty = t >> 4;

    unsigned long long acc2[8][4];
#pragma unroll
    for (int i = 0; i < 8; i++)
#pragma unroll
        for (int j = 0; j < 4; j++) acc2[i][j] = 0ULL;

    const float* Ag = Xin + (size_t)(m0 + lr) * ICC;
    const float* Bg = Wp  + (size_t)(n0 + lr) * ICC;

    for (int k0 = 0; k0 < ICC; k0 += PBK) {
        float4 a0 = __ldg((const float4*)(Ag + k0 + lc));
        float4 a1 = __ldg((const float4*)(Ag + k0 + lc + 4));
        float4 b0 = __ldg((const float4*)(Bg + k0 + lc));
        float4 b1 = __ldg((const float4*)(Bg + k0 + lc + 4));
        As[lc+0][lr] = a0.x; As[lc+1][lr] = a0.y; As[lc+2][lr] = a0.z; As[lc+3][lr] = a0.w;
        As[lc+4][lr] = a1.x; As[lc+5][lr] = a1.y; As[lc+6][lr] = a1.z; As[lc+7][lr] = a1.w;
        Bs[lc+0][lr] = b0.x; Bs[lc+1][lr] = b0.y; Bs[lc+2][lr] = b0.z; Bs[lc+3][lr] = b0.w;
        Bs[lc+4][lr] = b1.x; Bs[lc+5][lr] = b1.y; Bs[lc+6][lr] = b1.z; Bs[lc+7][lr] = b1.w;
        __syncthreads();
#pragma unroll
        for (int k = 0; k < PBK; k++) {
            float4 am0 = *(const float4*)&As[k][ty * 8];
            float4 am1 = *(const float4*)&As[k][ty * 8 + 4];
            ulonglong2 bu0 = *(const ulonglong2*)&Bs[k][tx * 8];
            ulonglong2 bu1 = *(const ulonglong2*)&Bs[k][tx * 8 + 4];
            float am[8] = {am0.x, am0.y, am0.z, am0.w, am1.x, am1.y, am1.z, am1.w};
#pragma unroll
            for (int i = 0; i < 8; i++) {
                unsigned long long ad = dup2(am[i]);
                fma2(acc2[i][0], ad, bu0.x);
                fma2(acc2[i][1], ad, bu0.y);
                fma2(acc2[i][2], ad, bu1.x);
                fma2(acc2[i][3], ad, bu1.y);
            }
        }
        __syncthreads();
    }

    float4 bv0 = __ldg((const float4*)(bp + n0 + tx * 8));
    float4 bv1 = __ldg((const float4*)(bp + n0 + tx * 8 + 4));
#pragma unroll
    for (int i = 0; i < 8; i++) {
        size_t row = (size_t)(m0 + ty * 8 + i);
        float2 p0 = unpk(acc2[i][0]);
        float2 p1 = unpk(acc2[i][1]);
        float2 p2 = unpk(acc2[i][2]);
        float2 p3 = unpk(acc2[i][3]);
        float4 o0 = make_float4(p0.x + bv0.x, p0.y + bv0.y, p1.x + bv0.z, p1.y + bv0.w);
        float4 o1 = make_float4(p2.x + bv1.x, p2.y + bv1.y, p3.x + bv1.z, p3.y + bv1.w);
        *(float4*)&g_xproj[row * HCC + n0 + tx * 8]     = o0;
        *(float4*)&g_xproj[row * HCC + n0 + tx * 8 + 4] = o1;
    }
}

// ---------------------------------------------------------------------------
// Fused 2-layer recurrence, critical/slack split.
// CTA(bg,rank): batches [4bg,+4), channels [32r,+32). Superstep s in [0,TT]:
// CRITICAL: wait bar0(h0[s-1]) -> ldcg h0 -> C-dot (h1[s-2], staged; covers
//   the ldcg) -> stage h0 -> A-dot -> tanh h0[s] -> publish g_h0 -> arrive
//   bar0. Peers unblock here.
// SLACK: B-dot -> h1[s-1] epilogue -> publish g_h1 + arrive bar1 -> ys store
//   -> wait bar1 + restage h1[s-1] for next step's C-dot.
// Barriers: bar0[2]/bar1[2] parity mbars, expect=16, R15 primitives.
// ---------------------------------------------------------------------------
__global__ __launch_bounds__(RTH, 1)
void fused_kernel(const float* __restrict__ Wi, const float* __restrict__ Wh,
                  const float* __restrict__ bi, const float* __restrict__ bh,
                  float* __restrict__ out)
{
    extern __shared__ char sm[];
    float4* wi1s = (float4*)(sm + OFF_WI1);
    float*  Hs0  = (float*)(sm + OFF_HS0);       // [2][4*512]
    float*  Hs1  = (float*)(sm + OFF_HS1);       // [2][4*512]
    float*  redA = (float*)(sm + OFF_RED);
    float*  redB = redA + 1024;
    float*  redC = redA + 2048;
    __shared__ __align__(8) unsigned long long mbar[4];  // A0 A1 B0 B1

    const int t    = threadIdx.x;
    const int bid  = blockIdx.x;
    const int bg   = bid >> 4;
    const int rank = bid & 15;
    const int b0   = bg * BPG;
    const int c0   = rank * CPG;
    const int w    = t >> 5;        // k-slice [64w, 64w+64)
    const int l    = t & 31;        // channel within CTA
    const int gc   = c0 + l;

    const float* Wh1g = Wh + (size_t)HCC * HCC;
    const float* Wi1g = Wi + (size_t)HCC * ICC;
    float* out_hs0 = out;
    float* out_hs1 = out + BB * HCC;
    float* out_inp = out + (size_t)LLL * BB * HCC;

    // Step-invariant weights -> registers.
    ulonglong2 wr0[16], wr1[16];
    {
        const ulonglong2* p0 = (const ulonglong2*)(Wh   + (size_t)gc * HCC + w * 64);
        const ulonglong2* p1 = (const ulonglong2*)(Wh1g + (size_t)gc * HCC + w * 64);
#pragma unroll
        for (int j = 0; j < 16; j++) { wr0[j] = p0[j]; wr1[j] = p1[j]; }
    }
    // Wi1 slice -> pad-129 smem.
    {
        const float4* si = (const float4*)Wi1g + (size_t)c0 * (HCC / 4);
        for (int idx = t; idx < CPG * (HCC / 4); idx += RTH)
            wi1s[(idx >> 7) * 129 + (idx & 127)] = __ldg(si + idx);
    }
    // Zero staging: Hs0 buf0 (h0[-1]=0), Hs1 both bufs (h1[-1]=0).
    for (int i = t; i < BPG * HCC; i += RTH) Hs0[i] = 0.f;
    for (int i = t; i < 2 * BPG * HCC; i += RTH) Hs1[i] = 0.f;

    const uint32_t mbA0 = smem_u32(&mbar[0]);
    const uint32_t mbA1 = smem_u32(&mbar[1]);
    const uint32_t mbB0 = smem_u32(&mbar[2]);
    const uint32_t mbB1 = smem_u32(&mbar[3]);
    if (t == 0) {
        mbar_init(mbA0, CS); mbar_init(mbA1, CS);
        mbar_init(mbB0, CS); mbar_init(mbB1, CS);
    }
    __syncthreads();
    CL_SYNC();

    // Remote arrive targets (t < 16: rank t).
    const uint32_t raA0 = (t < CS) ? mapa_u32(mbA0, (uint32_t)t) : 0u;
    const uint32_t raA1 = (t < CS) ? mapa_u32(mbA1, (uint32_t)t) : 0u;
    const uint32_t raB0 = (t < CS) ? mapa_u32(mbB0, (uint32_t)t) : 0u;
    const uint32_t raB1 = (t < CS) ? mapa_u32(mbB1, (uint32_t)t) : 0u;

    // Epilogue constants (t<128): b = t>>5, ch = t&31.
    const int ec = t & 31;
    float bh0v = 0.f, bi1v = 0.f, bh1v = 0.f;
    if (t < 128) {
        bh0v = __ldg(bh + c0 + ec);
        bi1v = __ldg(bi + HCC + c0 + ec);
        bh1v = __ldg(bh + HCC + c0 + ec);
    }
    const size_t eoi = (size_t)(b0 + (t >> 5)) * HCC + c0 + ec;

    const ulonglong2* wip = (const ulonglong2*)wi1s + (size_t)l * 129 + w * 16;
    int pA0 = 0, pA1 = 0, pB0 = 0, pB1 = 0;

    for (int s = 0; s <= TT; s++) {
        // xproj prefetch (independent of the h chain).
        float xp0v = 0.f;
        if (t < 128 && s < TT)
            xp0v = __ldg(&g_xproj[(size_t)s * (BB * HCC) + eoi]);

        // ---- CRITICAL LANE ----
        float4 h0ra, h0rb;
        if (s >= 1) {
            if ((s - 1) & 1) { mbar_wait_parity(mbA1, (uint32_t)pA1); pA1 ^= 1; }
            else             { mbar_wait_parity(mbA0, (uint32_t)pA0); pA0 ^= 1; }
            const float4* s0 = (const float4*)(g_h0[(s - 1) & 1] + b0 * HCC);
            h0ra = __ldcg(s0 + t);           // in flight during the C-dot
            h0rb = __ldcg(s0 + t + 256);

            // C-dot: h1[s-2] from Hs1[(s-1)&1].
            const ulonglong2* h1p =
                (const ulonglong2*)(Hs1 + ((s - 1) & 1) * (BPG * HCC) + w * 64);
            unsigned long long aC0=0,aC1=0,aC2=0,aC3=0;
#pragma unroll
            for (int j = 0; j < 16; j++) {
                ulonglong2 w1 = wr1[j];
                ulonglong2 h10 = h1p[j];
                ulonglong2 h11 = h1p[j + 128];
                ulonglong2 h12 = h1p[j + 256];
                ulonglong2 h13 = h1p[j + 384];
                fma2(aC0, w1.x, h10.x); fma2(aC0, w1.y, h10.y);
                fma2(aC1, w1.x, h11.x); fma2(aC1, w1.y, h11.y);
                fma2(aC2, w1.x, h12.x); fma2(aC2, w1.y, h12.y);
                fma2(aC3, w1.x, h13.x); fma2(aC3, w1.y, h13.y);
            }
            float2 q;
            q = unpk(aC0); redC[w*128 +  0 + l] = q.x + q.y;
            q = unpk(aC1); redC[w*128 + 32 + l] = q.x + q.y;
            q = unpk(aC2); redC[w*128 + 64 + l] = q.x + q.y;
            q = unpk(aC3); redC[w*128 + 96 + l] = q.x + q.y;

            // Stage h0[s-1] into Hs0[s&1].
            float4* hd = (float4*)(Hs0 + (s & 1) * (BPG * HCC));
            hd[t] = h0ra; hd[t + 256] = h0rb;
        }
        __syncthreads();

        // A-dot: h0[s-1] from Hs0[s&1].
        const ulonglong2* h0p =
            (const ulonglong2*)(Hs0 + (s & 1) * (BPG * HCC) + w * 64);
        {
            unsigned long long aA0=0,aA1=0,aA2=0,aA3=0;
#pragma unroll
            for (int j = 0; j < 16; j++) {
                ulonglong2 w0 = wr0[j];
                ulonglong2 h00 = h0p[j];
                ulonglong2 h01 = h0p[j + 128];
                ulonglong2 h02 = h0p[j + 256];
                ulonglong2 h03 = h0p[j + 384];
                fma2(aA0, w0.x, h00.x); fma2(aA0, w0.y, h00.y);
                fma2(aA1, w0.x, h01.x); fma2(aA1, w0.y, h01.y);
                fma2(aA2, w0.x, h02.x); fma2(aA2, w0.y, h02.y);
                fma2(aA3, w0.x, h03.x); fma2(aA3, w0.y, h03.y);
            }
            float2 q;
            q = unpk(aA0); redA[w*128 +  0 + l] = q.x + q.y;
            q = unpk(aA1); redA[w*128 + 32 + l] = q.x + q.y;
            q = unpk(aA2); redA[w*128 + 64 + l] = q.x + q.y;
            q = unpk(aA3); redA[w*128 + 96 + l] = q.x + q.y;
        }
        __syncthreads();

        // Epilogue A: tanh + publish h0[s].
        if (t < 128 && s < TT) {
            float sA = 0.f;
#pragma unroll
            for (int k = 0; k < 8; k++) sA += redA[k * 128 + t];
            float h0n = tanhf(xp0v + bh0v + sA);
            __stcg(&g_h0[s & 1][eoi], h0n);
            if (s == TT - 1) out_hs0[eoi] = h0n;
        }
        __syncthreads();
        if (s < TT && t < CS)
            mbar_arrive_remote((s & 1) ? raA1 : raA0);   // peers unblock here

        // ---- SLACK LANE ----
        if (s >= 1) {
            // B-dot: Wi1 . h0[s-1].
            unsigned long long aB0=0,aB1=0,aB2=0,aB3=0;
#pragma unroll
            for (int j = 0; j < 16; j++) {
                ulonglong2 wiv = wip[j];
                ulonglong2 h00 = h0p[j];
                ulonglong2 h01 = h0p[j + 128];
                ulonglong2 h02 = h0p[j + 256];
                ulonglong2 h03 = h0p[j + 384];
                fma2(aB0, wiv.x, h00.x); fma2(aB0, wiv.y, h00.y);
                fma2(aB1, wiv.x, h01.x); fma2(aB1, wiv.y, h01.y);
                fma2(aB2, wiv.x, h02.x); fma2(aB2, wiv.y, h02.y);
                fma2(aB3, wiv.x, h03.x); fma2(aB3, wiv.y, h03.y);
            }
            float2 q;
            q = unpk(aB0); redB[w*128 +  0 + l] = q.x + q.y;
            q = unpk(aB1); redB[w*128 + 32 + l] = q.x + q.y;
            q = unpk(aB2); redB[w*128 + 64 + l] = q.x + q.y;
            q = unpk(aB3); redB[w*128 + 96 + l] = q.x + q.y;
            __syncthreads();

            // Epilogue 1: h1[s-1] = tanh(bi1 + B + bh1 + C); publish + out.
            if (t < 128) {
                float sB = 0.f, sC = 0.f;
#pragma unroll
                for (int k = 0; k < 8; k++) {
                    sB += redB[k * 128 + t];
                    sC += redC[k * 128 + t];
                }
                float h1n = tanhf(bi1v + sB + bh1v + sC);
                if (s < TT) __stcg(&g_h1[s & 1][eoi], h1n);
                out_inp[(size_t)(s - 1) * (BB * HCC) + eoi] = h1n;
                if (s == TT) out_hs1[eoi] = h1n;
            }
            __syncthreads();

            if (s < TT) {
                if (t < CS)
                    mbar_arrive_remote((s & 1) ? raB1 : raB0);
                // Restage h1[s-1] for next step's C-dot (wait is slack-
                // tolerant: producers published one slack-section ago).
                if (s & 1) { mbar_wait_parity(mbB1, (uint32_t)pB1); pB1 ^= 1; }
                else       { mbar_wait_parity(mbB0, (uint32_t)pB0); pB0 ^= 1; }
                const float4* s1 = (const float4*)(g_h1[s & 1] + b0 * HCC);
                float4 c4 = __ldcg(s1 + t);
                float4 d4 = __ldcg(s1 + t + 256);
                float4* hd1 = (float4*)(Hs1 + (s & 1) * (BPG * HCC));
                hd1[t] = c4; hd1[t + 256] = d4;
            }
            __syncthreads();   // Hs1 staged before next step's C-dot
        }
    }

    CL_SYNC();
}

// ---------------------------------------------------------------------------
// Output layout: [hs (L,B,HC) | inp (T,B,HC)]
// ---------------------------------------------------------------------------
extern "C" void kernel_launch(void* const* d_in, const int* in_sizes, int n_in,
                              void* d_out, int out_size) {
    const float* x  = (const float*)d_in[0];
    const float* Wi = (const float*)d_in[1];
    const float* bi = (const float*)d_in[2];
    const float* Wh = (const float*)d_in[3];
    const float* bh = (const float*)d_in[4];
    float* out = (float*)d_out;

    cudaFuncSetAttribute(fused_kernel,
                         cudaFuncAttributeMaxDynamicSharedMemorySize, FSMEM);
    cudaFuncSetAttribute(fused_kernel,
                         cudaFuncAttributeNonPortableClusterSizeAllowed, 1);

    dim3 pg(HCC / PBN, (TT * BB) / PBM);  // (4, 512)
    proj_kernel<<<pg, 256>>>(x, Wi, bi);  // layer-0 input projection only

    cudaLaunchConfig_t cfg = {};
    cfg.gridDim  = dim3(NCTA, 1, 1);
    cfg.blockDim = dim3(RTH, 1, 1);
    cfg.dynamicSmemBytes = FSMEM;
    cfg.stream = 0;
    cudaLaunchAttribute attrs[1];
    attrs[0].id = cudaLaunchAttributeClusterDimension;
    attrs[0].val.clusterDim.x = CS;
    attrs[0].val.clusterDim.y = 1;
    attrs[0].val.clusterDim.z = 1;
    cfg.attrs = attrs;
    cfg.numAttrs = 1;
    cudaLaunchKernelEx(&cfg, fused_kernel, Wi, Wh, bi, bh, out);
}